// round 15
// baseline (speedup 1.0000x reference)
#include <cuda_runtime.h>

// FlexiblePDHGFront: N=1M independent points, MLP encode + 10 unrolled PDHG
// steps with learned prox. Fully compute-bound (10.2 G MAC vs 72 MB HBM).
// Strategy: 2 points per thread, everything packed as f32x2, all matvecs via
// fma.rn.f32x2 (FFMA2 = full-rate FP32 on sm_103a), weights duplicated into
// both halves in shared memory and fetched 2-at-a-time via LDS.128.

typedef unsigned long long u64;

#define EE 16
#define HID 32
#define JSTEPS 10
#define TPB 128

__device__ __forceinline__ u64 pk(float lo, float hi) {
    u64 r; asm("mov.b64 %0, {%1, %2};" : "=l"(r) : "f"(lo), "f"(hi)); return r;
}
__device__ __forceinline__ void upk(u64 v, float& lo, float& hi) {
    asm("mov.b64 {%0, %1}, %2;" : "=f"(lo), "=f"(hi) : "l"(v));
}
__device__ __forceinline__ u64 fma2(u64 a, u64 b, u64 c) {
    u64 r; asm("fma.rn.f32x2 %0, %1, %2, %3;" : "=l"(r) : "l"(a), "l"(b), "l"(c)); return r;
}
__device__ __forceinline__ u64 add2(u64 a, u64 b) {
    u64 r; asm("add.rn.f32x2 %0, %1, %2;" : "=l"(r) : "l"(a), "l"(b)); return r;
}
__device__ __forceinline__ u64 mul2(u64 a, u64 b) {
    u64 r; asm("mul.rn.f32x2 %0, %1, %2;" : "=l"(r) : "l"(a), "l"(b)); return r;
}
__device__ __forceinline__ u64 relu2(u64 v) {
    float a, b; upk(v, a, b);
    return pk(fmaxf(a, 0.0f), fmaxf(b, 0.0f));
}
__device__ __forceinline__ float tanh_acc(float v) {
    // accurate enough tanh (avoid fast-math tanh.approx ambiguity):
    // clamp so __expf never overflows; saturated anyway beyond |v|~9.
    v = fminf(fmaxf(v, -15.0f), 15.0f);
    float e = __expf(2.0f * v);
    return (e - 1.0f) / (e + 1.0f);
}

__global__ void __launch_bounds__(TPB) pdhg_kernel(
    const float* __restrict__ gx,  const float* __restrict__ G,   const float* __restrict__ hb,
    const float* __restrict__ W1,  const float* __restrict__ b1,
    const float* __restrict__ W2,  const float* __restrict__ b2,
    const float* __restrict__ Wmu, const float* __restrict__ bmu,
    const float* __restrict__ Wy,  const float* __restrict__ by,
    const float* __restrict__ Wp1, const float* __restrict__ bp1,
    const float* __restrict__ Wp2, const float* __restrict__ bp2,
    float* __restrict__ out, int npairs)
{
    // All weights duplicated into both f32x2 halves. Interleaved layouts so
    // one LDS.128 feeds two FMA2s (or both rows of a 2-row matrix).
    __shared__ __align__(16) u64 sW1i[2 * HID];    // (W1[0][k], W1[1][k]) pairs
    __shared__ __align__(16) u64 sb1[HID];
    __shared__ __align__(16) u64 sW2[HID * HID];   // row-major [k][j]
    __shared__ __align__(16) u64 sb2[HID];
    __shared__ __align__(16) u64 sWmu[HID * EE];   // row-major [j][e]
    __shared__ __align__(16) u64 sbmu[EE];
    __shared__ __align__(16) u64 sWy[HID * 2];     // (Wy[j][0], Wy[j][1]) pairs
    __shared__ __align__(16) u64 sby[2];
    __shared__ __align__(16) u64 sWp1i[2 * HID];   // (Wp1[0][h], Wp1[1][h]) pairs
    __shared__ __align__(16) u64 sbp1[HID];
    __shared__ __align__(16) u64 sWp2[HID * EE];   // row-major [h][e]
    __shared__ __align__(16) u64 sbp2[EE];
    __shared__ __align__(16) u64 sGxy[2 * EE];     // (Gx[e], Gy[e]) pairs
    __shared__ __align__(16) u64 sTh[EE];          // -TAU * h[e]

    const int tid = threadIdx.x;
    for (int i = tid; i < HID * HID; i += TPB) sW2[i] = pk(W2[i], W2[i]);
    for (int i = tid; i < HID * EE; i += TPB) {
        sWmu[i] = pk(Wmu[i], Wmu[i]);
        sWp2[i] = pk(Wp2[i], Wp2[i]);
    }
    for (int i = tid; i < 2 * HID; i += TPB) {
        float w1 = W1[(i & 1) * HID + (i >> 1)];  sW1i[i]  = pk(w1, w1);
        float wp = Wp1[(i & 1) * HID + (i >> 1)]; sWp1i[i] = pk(wp, wp);
        sWy[i] = pk(Wy[i], Wy[i]);
    }
    for (int i = tid; i < HID; i += TPB) {
        sb1[i]  = pk(b1[i],  b1[i]);
        sb2[i]  = pk(b2[i],  b2[i]);
        sbp1[i] = pk(bp1[i], bp1[i]);
    }
    for (int i = tid; i < 2 * EE; i += TPB) sGxy[i] = pk(G[i], G[i]);
    for (int i = tid; i < EE; i += TPB) {
        sbmu[i] = pk(bmu[i], bmu[i]);
        sbp2[i] = pk(bp2[i], bp2[i]);
        float th = -0.5f * hb[i];  // -TAU*h
        sTh[i] = pk(th, th);
    }
    if (tid < 2) sby[tid] = pk(by[tid], by[tid]);
    __syncthreads();

    const int gid = blockIdx.x * TPB + tid;
    if (gid >= npairs) return;

    // Two adjacent points per thread: x[2g], x[2g+1] as one float4.
    const float4 xv = reinterpret_cast<const float4*>(gx)[gid];
    const u64 xa = pk(xv.x, xv.z);  // x component 0 of both points
    const u64 xb = pk(xv.y, xv.w);  // x component 1 of both points

    // ---------------- encoder: feats2 = relu(relu(x@W1+b1)@W2 + b2) ----------------
    u64 f2[HID];
    #pragma unroll
    for (int j = 0; j < HID; j += 2) {
        ulonglong2 b = *reinterpret_cast<const ulonglong2*>(&sb2[j]);
        f2[j] = b.x; f2[j + 1] = b.y;
    }
    #pragma unroll
    for (int k = 0; k < HID; ++k) {
        ulonglong2 w1 = *reinterpret_cast<const ulonglong2*>(&sW1i[2 * k]);
        u64 f1 = relu2(fma2(xa, w1.x, fma2(xb, w1.y, sb1[k])));
        #pragma unroll
        for (int j = 0; j < HID; j += 2) {
            ulonglong2 w = *reinterpret_cast<const ulonglong2*>(&sW2[k * HID + j]);
            f2[j]     = fma2(f1, w.x, f2[j]);
            f2[j + 1] = fma2(f1, w.y, f2[j + 1]);
        }
    }

    // ---------------- heads: mu = relu(f@Wmu+bmu), y = tanh(f@Wy+by) ----------------
    u64 mu[EE], y0, y1;
    #pragma unroll
    for (int e = 0; e < EE; ++e) mu[e] = sbmu[e];
    y0 = sby[0]; y1 = sby[1];
    #pragma unroll
    for (int j = 0; j < HID; ++j) {
        u64 f = relu2(f2[j]);
        ulonglong2 wy = *reinterpret_cast<const ulonglong2*>(&sWy[2 * j]);
        y0 = fma2(f, wy.x, y0);
        y1 = fma2(f, wy.y, y1);
        #pragma unroll
        for (int e = 0; e < EE; e += 2) {
            ulonglong2 w = *reinterpret_cast<const ulonglong2*>(&sWmu[j * EE + e]);
            mu[e]     = fma2(f, w.x, mu[e]);
            mu[e + 1] = fma2(f, w.y, mu[e + 1]);
        }
    }
    #pragma unroll
    for (int e = 0; e < EE; ++e) mu[e] = relu2(mu[e]);
    {
        float a, b;
        upk(y0, a, b); y0 = pk(tanh_acc(a), tanh_acc(b));
        upk(y1, a, b); y1 = pk(tanh_acc(a), tanh_acc(b));
    }

    const u64 C05 = pk(0.5f, 0.5f);    // TAU == SIGMA == RES == 0.5
    const u64 N05 = pk(-0.5f, -0.5f);

    // ta[e] = TAU * (x . G_e - h_e)
    u64 ta[EE];
    #pragma unroll
    for (int e = 0; e < EE; ++e) {
        ulonglong2 g = *reinterpret_cast<const ulonglong2*>(&sGxy[2 * e]);
        u64 xg = fma2(xa, g.x, mul2(xb, g.y));
        ta[e] = fma2(C05, xg, sTh[e]);
    }

    // ---------------- 10 PDHG steps (rolled: keep body inside I-cache) ----------------
    #pragma unroll 1
    for (int it = 0; it < JSTEPS; ++it) {
        // v = mu @ G ; y = normalize_ball(y + SIGMA*v)
        u64 v0, v1;
        {
            ulonglong2 g0 = *reinterpret_cast<const ulonglong2*>(&sGxy[0]);
            v0 = mul2(mu[0], g0.x); v1 = mul2(mu[0], g0.y);
            #pragma unroll
            for (int e = 1; e < EE; ++e) {
                ulonglong2 g = *reinterpret_cast<const ulonglong2*>(&sGxy[2 * e]);
                v0 = fma2(mu[e], g.x, v0);
                v1 = fma2(mu[e], g.y, v1);
            }
        }
        y0 = fma2(C05, v0, y0);
        y1 = fma2(C05, v1, y1);
        {
            u64 n2 = fma2(y0, y0, mul2(y1, y1));
            float na, nb; upk(n2, na, nb);
            float sa = (na > 1.0f) ? rsqrtf(na) : 1.0f;
            float sb = (nb > 1.0f) ? rsqrtf(nb) : 1.0f;
            u64 s = pk(sa, sb);
            y0 = mul2(y0, s); y1 = mul2(y1, s);
        }
        // mu += TAU*a - TAU*(y @ G^T)
        #pragma unroll
        for (int e = 0; e < EE; ++e) {
            ulonglong2 g = *reinterpret_cast<const ulonglong2*>(&sGxy[2 * e]);
            u64 yg = fma2(y0, g.x, mul2(y1, g.y));
            mu[e] = add2(mu[e], fma2(N05, yg, ta[e]));
        }
        // z = mu @ G
        u64 z0, z1;
        {
            ulonglong2 g0 = *reinterpret_cast<const ulonglong2*>(&sGxy[0]);
            z0 = mul2(mu[0], g0.x); z1 = mul2(mu[0], g0.y);
            #pragma unroll
            for (int e = 1; e < EE; ++e) {
                ulonglong2 g = *reinterpret_cast<const ulonglong2*>(&sGxy[2 * e]);
                z0 = fma2(mu[e], g.x, z0);
                z1 = fma2(mu[e], g.y, z1);
            }
        }
        // delta = relu(z@Wp1 + bp1) @ Wp2 + bp2   (dominant: 512 MAC/step)
        u64 d[EE];
        #pragma unroll
        for (int e = 0; e < EE; e += 2) {
            ulonglong2 b = *reinterpret_cast<const ulonglong2*>(&sbp2[e]);
            d[e] = b.x; d[e + 1] = b.y;
        }
        #pragma unroll
        for (int hh = 0; hh < HID; ++hh) {
            ulonglong2 wp = *reinterpret_cast<const ulonglong2*>(&sWp1i[2 * hh]);
            u64 hv = relu2(fma2(z0, wp.x, fma2(z1, wp.y, sbp1[hh])));
            #pragma unroll
            for (int e = 0; e < EE; e += 2) {
                ulonglong2 w = *reinterpret_cast<const ulonglong2*>(&sWp2[hh * EE + e]);
                d[e]     = fma2(hv, w.x, d[e]);
                d[e + 1] = fma2(hv, w.y, d[e + 1]);
            }
        }
        // mu = project_mu(mu + RES*delta): clamp >= 0, then scale so ||mu@G|| <= 1
        #pragma unroll
        for (int e = 0; e < EE; ++e) mu[e] = relu2(fma2(C05, d[e], mu[e]));
        {
            ulonglong2 g0 = *reinterpret_cast<const ulonglong2*>(&sGxy[0]);
            v0 = mul2(mu[0], g0.x); v1 = mul2(mu[0], g0.y);
            #pragma unroll
            for (int e = 1; e < EE; ++e) {
                ulonglong2 g = *reinterpret_cast<const ulonglong2*>(&sGxy[2 * e]);
                v0 = fma2(mu[e], g.x, v0);
                v1 = fma2(mu[e], g.y, v1);
            }
            u64 n2 = fma2(v0, v0, mul2(v1, v1));
            float na, nb; upk(n2, na, nb);
            float sa = (na > 1.0f) ? rsqrtf(na) : 1.0f;
            float sb = (nb > 1.0f) ? rsqrtf(nb) : 1.0f;
            u64 s = pk(sa, sb);
            #pragma unroll
            for (int e = 0; e < EE; ++e) mu[e] = mul2(mu[e], s);
        }
    }

    // ---------------- final project_mu (mu already >= 0 from loop) ----------------
    {
        ulonglong2 g0 = *reinterpret_cast<const ulonglong2*>(&sGxy[0]);
        u64 v0 = mul2(mu[0], g0.x), v1 = mul2(mu[0], g0.y);
        #pragma unroll
        for (int e = 1; e < EE; ++e) {
            ulonglong2 g = *reinterpret_cast<const ulonglong2*>(&sGxy[2 * e]);
            v0 = fma2(mu[e], g.x, v0);
            v1 = fma2(mu[e], g.y, v1);
        }
        u64 n2 = fma2(v0, v0, mul2(v1, v1));
        float na, nb; upk(n2, na, nb);
        float sa = (na > 1.0f) ? rsqrtf(na) : 1.0f;
        float sb = (nb > 1.0f) ? rsqrtf(nb) : 1.0f;
        u64 s = pk(sa, sb);
        #pragma unroll
        for (int e = 0; e < EE; ++e) mu[e] = mul2(mu[e], s);
    }

    // ---------------- store: rows 2g and 2g+1 are 128B contiguous ----------------
    float r0[EE], r1[EE];
    #pragma unroll
    for (int e = 0; e < EE; ++e) upk(mu[e], r0[e], r1[e]);
    float4* o = reinterpret_cast<float4*>(out + (size_t)gid * 32);
    o[0] = make_float4(r0[0],  r0[1],  r0[2],  r0[3]);
    o[1] = make_float4(r0[4],  r0[5],  r0[6],  r0[7]);
    o[2] = make_float4(r0[8],  r0[9],  r0[10], r0[11]);
    o[3] = make_float4(r0[12], r0[13], r0[14], r0[15]);
    o[4] = make_float4(r1[0],  r1[1],  r1[2],  r1[3]);
    o[5] = make_float4(r1[4],  r1[5],  r1[6],  r1[7]);
    o[6] = make_float4(r1[8],  r1[9],  r1[10], r1[11]);
    o[7] = make_float4(r1[12], r1[13], r1[14], r1[15]);
}

extern "C" void kernel_launch(void* const* d_in, const int* in_sizes, int n_in,
                              void* d_out, int out_size) {
    (void)n_in; (void)out_size;
    const float* x   = (const float*)d_in[0];
    const float* G   = (const float*)d_in[1];
    const float* h   = (const float*)d_in[2];
    const float* W1  = (const float*)d_in[3];
    const float* b1  = (const float*)d_in[4];
    const float* W2  = (const float*)d_in[5];
    const float* b2  = (const float*)d_in[6];
    const float* Wmu = (const float*)d_in[7];
    const float* bmu = (const float*)d_in[8];
    const float* Wy  = (const float*)d_in[9];
    const float* by  = (const float*)d_in[10];
    const float* Wp1 = (const float*)d_in[11];
    const float* bp1 = (const float*)d_in[12];
    const float* Wp2 = (const float*)d_in[13];
    const float* bp2 = (const float*)d_in[14];

    const int n_points = in_sizes[0] / 2;   // x is [N, 2]
    const int npairs   = n_points / 2;      // 2 points per thread
    const int nblocks  = (npairs + TPB - 1) / TPB;

    pdhg_kernel<<<nblocks, TPB>>>(x, G, h, W1, b1, W2, b2, Wmu, bmu,
                                  Wy, by, Wp1, bp1, Wp2, bp2,
                                  (float*)d_out, npairs);
}

// round 16
// speedup vs baseline: 1.0039x; 1.0039x over previous
#include <cuda_runtime.h>

// FlexiblePDHGFront: N=1M independent points, MLP encode + 10 unrolled PDHG
// steps with learned prox. Fully compute-bound (10.2 G MAC vs 72 MB HBM).
// Strategy: 2 points per thread, everything packed as f32x2, all matvecs via
// fma.rn.f32x2 (FFMA2 = full-rate FP32 on sm_103a), weights duplicated into
// both halves in shared memory and fetched 2-at-a-time via LDS.128.

typedef unsigned long long u64;

#define EE 16
#define HID 32
#define JSTEPS 10
#define TPB 128

__device__ __forceinline__ u64 pk(float lo, float hi) {
    u64 r; asm("mov.b64 %0, {%1, %2};" : "=l"(r) : "f"(lo), "f"(hi)); return r;
}
__device__ __forceinline__ void upk(u64 v, float& lo, float& hi) {
    asm("mov.b64 {%0, %1}, %2;" : "=f"(lo), "=f"(hi) : "l"(v));
}
__device__ __forceinline__ u64 fma2(u64 a, u64 b, u64 c) {
    u64 r; asm("fma.rn.f32x2 %0, %1, %2, %3;" : "=l"(r) : "l"(a), "l"(b), "l"(c)); return r;
}
__device__ __forceinline__ u64 add2(u64 a, u64 b) {
    u64 r; asm("add.rn.f32x2 %0, %1, %2;" : "=l"(r) : "l"(a), "l"(b)); return r;
}
__device__ __forceinline__ u64 mul2(u64 a, u64 b) {
    u64 r; asm("mul.rn.f32x2 %0, %1, %2;" : "=l"(r) : "l"(a), "l"(b)); return r;
}
__device__ __forceinline__ u64 relu2(u64 v) {
    float a, b; upk(v, a, b);
    return pk(fmaxf(a, 0.0f), fmaxf(b, 0.0f));
}
__device__ __forceinline__ float tanh_acc(float v) {
    // accurate enough tanh (avoid fast-math tanh.approx ambiguity):
    // clamp so __expf never overflows; saturated anyway beyond |v|~9.
    v = fminf(fmaxf(v, -15.0f), 15.0f);
    float e = __expf(2.0f * v);
    return (e - 1.0f) / (e + 1.0f);
}

__global__ void __launch_bounds__(TPB) pdhg_kernel(
    const float* __restrict__ gx,  const float* __restrict__ G,   const float* __restrict__ hb,
    const float* __restrict__ W1,  const float* __restrict__ b1,
    const float* __restrict__ W2,  const float* __restrict__ b2,
    const float* __restrict__ Wmu, const float* __restrict__ bmu,
    const float* __restrict__ Wy,  const float* __restrict__ by,
    const float* __restrict__ Wp1, const float* __restrict__ bp1,
    const float* __restrict__ Wp2, const float* __restrict__ bp2,
    float* __restrict__ out, int npairs)
{
    // All weights duplicated into both f32x2 halves. Interleaved layouts so
    // one LDS.128 feeds two FMA2s (or both rows of a 2-row matrix).
    __shared__ __align__(16) u64 sW1i[2 * HID];    // (W1[0][k], W1[1][k]) pairs
    __shared__ __align__(16) u64 sb1[HID];
    __shared__ __align__(16) u64 sW2[HID * HID];   // row-major [k][j]
    __shared__ __align__(16) u64 sb2[HID];
    __shared__ __align__(16) u64 sWmu[HID * EE];   // row-major [j][e]
    __shared__ __align__(16) u64 sbmu[EE];
    __shared__ __align__(16) u64 sWy[HID * 2];     // (Wy[j][0], Wy[j][1]) pairs
    __shared__ __align__(16) u64 sby[2];
    __shared__ __align__(16) u64 sWp1i[2 * HID];   // (Wp1[0][h], Wp1[1][h]) pairs
    __shared__ __align__(16) u64 sbp1[HID];
    __shared__ __align__(16) u64 sWp2[HID * EE];   // row-major [h][e]
    __shared__ __align__(16) u64 sbp2[EE];
    __shared__ __align__(16) u64 sGxy[2 * EE];     // (Gx[e], Gy[e]) pairs
    __shared__ __align__(16) u64 sTh[EE];          // -TAU * h[e]

    const int tid = threadIdx.x;
    for (int i = tid; i < HID * HID; i += TPB) sW2[i] = pk(W2[i], W2[i]);
    for (int i = tid; i < HID * EE; i += TPB) {
        sWmu[i] = pk(Wmu[i], Wmu[i]);
        sWp2[i] = pk(Wp2[i], Wp2[i]);
    }
    for (int i = tid; i < 2 * HID; i += TPB) {
        float w1 = W1[(i & 1) * HID + (i >> 1)];  sW1i[i]  = pk(w1, w1);
        float wp = Wp1[(i & 1) * HID + (i >> 1)]; sWp1i[i] = pk(wp, wp);
        sWy[i] = pk(Wy[i], Wy[i]);
    }
    for (int i = tid; i < HID; i += TPB) {
        sb1[i]  = pk(b1[i],  b1[i]);
        sb2[i]  = pk(b2[i],  b2[i]);
        sbp1[i] = pk(bp1[i], bp1[i]);
    }
    for (int i = tid; i < 2 * EE; i += TPB) sGxy[i] = pk(G[i], G[i]);
    for (int i = tid; i < EE; i += TPB) {
        sbmu[i] = pk(bmu[i], bmu[i]);
        sbp2[i] = pk(bp2[i], bp2[i]);
        float th = -0.5f * hb[i];  // -TAU*h
        sTh[i] = pk(th, th);
    }
    if (tid < 2) sby[tid] = pk(by[tid], by[tid]);
    __syncthreads();

    const int gid = blockIdx.x * TPB + tid;
    if (gid >= npairs) return;

    // Two adjacent points per thread: x[2g], x[2g+1] as one float4.
    const float4 xv = reinterpret_cast<const float4*>(gx)[gid];
    const u64 xa = pk(xv.x, xv.z);  // x component 0 of both points
    const u64 xb = pk(xv.y, xv.w);  // x component 1 of both points

    // ---------------- encoder: feats2 = relu(relu(x@W1+b1)@W2 + b2) ----------------
    u64 f2[HID];
    #pragma unroll
    for (int j = 0; j < HID; j += 2) {
        ulonglong2 b = *reinterpret_cast<const ulonglong2*>(&sb2[j]);
        f2[j] = b.x; f2[j + 1] = b.y;
    }
    #pragma unroll
    for (int k = 0; k < HID; ++k) {
        ulonglong2 w1 = *reinterpret_cast<const ulonglong2*>(&sW1i[2 * k]);
        u64 f1 = relu2(fma2(xa, w1.x, fma2(xb, w1.y, sb1[k])));
        #pragma unroll
        for (int j = 0; j < HID; j += 2) {
            ulonglong2 w = *reinterpret_cast<const ulonglong2*>(&sW2[k * HID + j]);
            f2[j]     = fma2(f1, w.x, f2[j]);
            f2[j + 1] = fma2(f1, w.y, f2[j + 1]);
        }
    }

    // ---------------- heads: mu = relu(f@Wmu+bmu), y = tanh(f@Wy+by) ----------------
    u64 mu[EE], y0, y1;
    #pragma unroll
    for (int e = 0; e < EE; ++e) mu[e] = sbmu[e];
    y0 = sby[0]; y1 = sby[1];
    #pragma unroll
    for (int j = 0; j < HID; ++j) {
        u64 f = relu2(f2[j]);
        ulonglong2 wy = *reinterpret_cast<const ulonglong2*>(&sWy[2 * j]);
        y0 = fma2(f, wy.x, y0);
        y1 = fma2(f, wy.y, y1);
        #pragma unroll
        for (int e = 0; e < EE; e += 2) {
            ulonglong2 w = *reinterpret_cast<const ulonglong2*>(&sWmu[j * EE + e]);
            mu[e]     = fma2(f, w.x, mu[e]);
            mu[e + 1] = fma2(f, w.y, mu[e + 1]);
        }
    }
    #pragma unroll
    for (int e = 0; e < EE; ++e) mu[e] = relu2(mu[e]);
    {
        float a, b;
        upk(y0, a, b); y0 = pk(tanh_acc(a), tanh_acc(b));
        upk(y1, a, b); y1 = pk(tanh_acc(a), tanh_acc(b));
    }

    const u64 C05 = pk(0.5f, 0.5f);    // TAU == SIGMA == RES == 0.5
    const u64 N05 = pk(-0.5f, -0.5f);

    // ta[e] = TAU * (x . G_e - h_e)
    u64 ta[EE];
    #pragma unroll
    for (int e = 0; e < EE; ++e) {
        ulonglong2 g = *reinterpret_cast<const ulonglong2*>(&sGxy[2 * e]);
        u64 xg = fma2(xa, g.x, mul2(xb, g.y));
        ta[e] = fma2(C05, xg, sTh[e]);
    }

    // ---------------- 10 PDHG steps (rolled: keep body inside I-cache) ----------------
    #pragma unroll 1
    for (int it = 0; it < JSTEPS; ++it) {
        // v = mu @ G ; y = normalize_ball(y + SIGMA*v)
        u64 v0, v1;
        {
            ulonglong2 g0 = *reinterpret_cast<const ulonglong2*>(&sGxy[0]);
            v0 = mul2(mu[0], g0.x); v1 = mul2(mu[0], g0.y);
            #pragma unroll
            for (int e = 1; e < EE; ++e) {
                ulonglong2 g = *reinterpret_cast<const ulonglong2*>(&sGxy[2 * e]);
                v0 = fma2(mu[e], g.x, v0);
                v1 = fma2(mu[e], g.y, v1);
            }
        }
        y0 = fma2(C05, v0, y0);
        y1 = fma2(C05, v1, y1);
        {
            u64 n2 = fma2(y0, y0, mul2(y1, y1));
            float na, nb; upk(n2, na, nb);
            float sa = (na > 1.0f) ? rsqrtf(na) : 1.0f;
            float sb = (nb > 1.0f) ? rsqrtf(nb) : 1.0f;
            u64 s = pk(sa, sb);
            y0 = mul2(y0, s); y1 = mul2(y1, s);
        }
        // mu += TAU*a - TAU*(y @ G^T)
        #pragma unroll
        for (int e = 0; e < EE; ++e) {
            ulonglong2 g = *reinterpret_cast<const ulonglong2*>(&sGxy[2 * e]);
            u64 yg = fma2(y0, g.x, mul2(y1, g.y));
            mu[e] = add2(mu[e], fma2(N05, yg, ta[e]));
        }
        // z = mu @ G
        u64 z0, z1;
        {
            ulonglong2 g0 = *reinterpret_cast<const ulonglong2*>(&sGxy[0]);
            z0 = mul2(mu[0], g0.x); z1 = mul2(mu[0], g0.y);
            #pragma unroll
            for (int e = 1; e < EE; ++e) {
                ulonglong2 g = *reinterpret_cast<const ulonglong2*>(&sGxy[2 * e]);
                z0 = fma2(mu[e], g.x, z0);
                z1 = fma2(mu[e], g.y, z1);
            }
        }
        // delta = relu(z@Wp1 + bp1) @ Wp2 + bp2   (dominant: 512 MAC/step)
        u64 d[EE];
        #pragma unroll
        for (int e = 0; e < EE; e += 2) {
            ulonglong2 b = *reinterpret_cast<const ulonglong2*>(&sbp2[e]);
            d[e] = b.x; d[e + 1] = b.y;
        }
        #pragma unroll
        for (int hh = 0; hh < HID; ++hh) {
            ulonglong2 wp = *reinterpret_cast<const ulonglong2*>(&sWp1i[2 * hh]);
            u64 hv = relu2(fma2(z0, wp.x, fma2(z1, wp.y, sbp1[hh])));
            #pragma unroll
            for (int e = 0; e < EE; e += 2) {
                ulonglong2 w = *reinterpret_cast<const ulonglong2*>(&sWp2[hh * EE + e]);
                d[e]     = fma2(hv, w.x, d[e]);
                d[e + 1] = fma2(hv, w.y, d[e + 1]);
            }
        }
        // mu = project_mu(mu + RES*delta): clamp >= 0, then scale so ||mu@G|| <= 1
        #pragma unroll
        for (int e = 0; e < EE; ++e) mu[e] = relu2(fma2(C05, d[e], mu[e]));
        {
            ulonglong2 g0 = *reinterpret_cast<const ulonglong2*>(&sGxy[0]);
            v0 = mul2(mu[0], g0.x); v1 = mul2(mu[0], g0.y);
            #pragma unroll
            for (int e = 1; e < EE; ++e) {
                ulonglong2 g = *reinterpret_cast<const ulonglong2*>(&sGxy[2 * e]);
                v0 = fma2(mu[e], g.x, v0);
                v1 = fma2(mu[e], g.y, v1);
            }
            u64 n2 = fma2(v0, v0, mul2(v1, v1));
            float na, nb; upk(n2, na, nb);
            float sa = (na > 1.0f) ? rsqrtf(na) : 1.0f;
            float sb = (nb > 1.0f) ? rsqrtf(nb) : 1.0f;
            u64 s = pk(sa, sb);
            #pragma unroll
            for (int e = 0; e < EE; ++e) mu[e] = mul2(mu[e], s);
        }
    }

    // ---------------- final project_mu (mu already >= 0 from loop) ----------------
    {
        ulonglong2 g0 = *reinterpret_cast<const ulonglong2*>(&sGxy[0]);
        u64 v0 = mul2(mu[0], g0.x), v1 = mul2(mu[0], g0.y);
        #pragma unroll
        for (int e = 1; e < EE; ++e) {
            ulonglong2 g = *reinterpret_cast<const ulonglong2*>(&sGxy[2 * e]);
            v0 = fma2(mu[e], g.x, v0);
            v1 = fma2(mu[e], g.y, v1);
        }
        u64 n2 = fma2(v0, v0, mul2(v1, v1));
        float na, nb; upk(n2, na, nb);
        float sa = (na > 1.0f) ? rsqrtf(na) : 1.0f;
        float sb = (nb > 1.0f) ? rsqrtf(nb) : 1.0f;
        u64 s = pk(sa, sb);
        #pragma unroll
        for (int e = 0; e < EE; ++e) mu[e] = mul2(mu[e], s);
    }

    // ---------------- store: rows 2g and 2g+1 are 128B contiguous ----------------
    float r0[EE], r1[EE];
    #pragma unroll
    for (int e = 0; e < EE; ++e) upk(mu[e], r0[e], r1[e]);
    float4* o = reinterpret_cast<float4*>(out + (size_t)gid * 32);
    o[0] = make_float4(r0[0],  r0[1],  r0[2],  r0[3]);
    o[1] = make_float4(r0[4],  r0[5],  r0[6],  r0[7]);
    o[2] = make_float4(r0[8],  r0[9],  r0[10], r0[11]);
    o[3] = make_float4(r0[12], r0[13], r0[14], r0[15]);
    o[4] = make_float4(r1[0],  r1[1],  r1[2],  r1[3]);
    o[5] = make_float4(r1[4],  r1[5],  r1[6],  r1[7]);
    o[6] = make_float4(r1[8],  r1[9],  r1[10], r1[11]);
    o[7] = make_float4(r1[12], r1[13], r1[14], r1[15]);
}

extern "C" void kernel_launch(void* const* d_in, const int* in_sizes, int n_in,
                              void* d_out, int out_size) {
    (void)n_in; (void)out_size;
    const float* x   = (const float*)d_in[0];
    const float* G   = (const float*)d_in[1];
    const float* h   = (const float*)d_in[2];
    const float* W1  = (const float*)d_in[3];
    const float* b1  = (const float*)d_in[4];
    const float* W2  = (const float*)d_in[5];
    const float* b2  = (const float*)d_in[6];
    const float* Wmu = (const float*)d_in[7];
    const float* bmu = (const float*)d_in[8];
    const float* Wy  = (const float*)d_in[9];
    const float* by  = (const float*)d_in[10];
    const float* Wp1 = (const float*)d_in[11];
    const float* bp1 = (const float*)d_in[12];
    const float* Wp2 = (const float*)d_in[13];
    const float* bp2 = (const float*)d_in[14];

    const int n_points = in_sizes[0] / 2;   // x is [N, 2]
    const int npairs   = n_points / 2;      // 2 points per thread
    const int nblocks  = (npairs + TPB - 1) / TPB;

    pdhg_kernel<<<nblocks, TPB>>>(x, G, h, W1, b1, W2, b2, Wmu, bmu,
                                  Wy, by, Wp1, bp1, Wp2, bp2,
                                  (float*)d_out, npairs);
}

// round 17
// speedup vs baseline: 1.0062x; 1.0023x over previous
#include <cuda_runtime.h>

// FlexiblePDHGFront: N=1M independent points, MLP encode + 10 unrolled PDHG
// steps with learned prox. Fully compute-bound (10.2 G MAC vs 72 MB HBM).
// Strategy: 2 points per thread, everything packed as f32x2, all matvecs via
// fma.rn.f32x2 (FFMA2 = full-rate FP32 on sm_103a), weights duplicated into
// both halves in shared memory and fetched 2-at-a-time via LDS.128.

typedef unsigned long long u64;

#define EE 16
#define HID 32
#define JSTEPS 10
#define TPB 128

__device__ __forceinline__ u64 pk(float lo, float hi) {
    u64 r; asm("mov.b64 %0, {%1, %2};" : "=l"(r) : "f"(lo), "f"(hi)); return r;
}
__device__ __forceinline__ void upk(u64 v, float& lo, float& hi) {
    asm("mov.b64 {%0, %1}, %2;" : "=f"(lo), "=f"(hi) : "l"(v));
}
__device__ __forceinline__ u64 fma2(u64 a, u64 b, u64 c) {
    u64 r; asm("fma.rn.f32x2 %0, %1, %2, %3;" : "=l"(r) : "l"(a), "l"(b), "l"(c)); return r;
}
__device__ __forceinline__ u64 add2(u64 a, u64 b) {
    u64 r; asm("add.rn.f32x2 %0, %1, %2;" : "=l"(r) : "l"(a), "l"(b)); return r;
}
__device__ __forceinline__ u64 mul2(u64 a, u64 b) {
    u64 r; asm("mul.rn.f32x2 %0, %1, %2;" : "=l"(r) : "l"(a), "l"(b)); return r;
}
__device__ __forceinline__ u64 relu2(u64 v) {
    float a, b; upk(v, a, b);
    return pk(fmaxf(a, 0.0f), fmaxf(b, 0.0f));
}
__device__ __forceinline__ float tanh_acc(float v) {
    // accurate enough tanh (avoid fast-math tanh.approx ambiguity):
    // clamp so __expf never overflows; saturated anyway beyond |v|~9.
    v = fminf(fmaxf(v, -15.0f), 15.0f);
    float e = __expf(2.0f * v);
    return (e - 1.0f) / (e + 1.0f);
}

__global__ void __launch_bounds__(TPB) pdhg_kernel(
    const float* __restrict__ gx,  const float* __restrict__ G,   const float* __restrict__ hb,
    const float* __restrict__ W1,  const float* __restrict__ b1,
    const float* __restrict__ W2,  const float* __restrict__ b2,
    const float* __restrict__ Wmu, const float* __restrict__ bmu,
    const float* __restrict__ Wy,  const float* __restrict__ by,
    const float* __restrict__ Wp1, const float* __restrict__ bp1,
    const float* __restrict__ Wp2, const float* __restrict__ bp2,
    float* __restrict__ out, int npairs)
{
    // All weights duplicated into both f32x2 halves. Interleaved layouts so
    // one LDS.128 feeds two FMA2s (or both rows of a 2-row matrix).
    __shared__ __align__(16) u64 sW1i[2 * HID];    // (W1[0][k], W1[1][k]) pairs
    __shared__ __align__(16) u64 sb1[HID];
    __shared__ __align__(16) u64 sW2[HID * HID];   // row-major [k][j]
    __shared__ __align__(16) u64 sb2[HID];
    __shared__ __align__(16) u64 sWmu[HID * EE];   // row-major [j][e]
    __shared__ __align__(16) u64 sbmu[EE];
    __shared__ __align__(16) u64 sWy[HID * 2];     // (Wy[j][0], Wy[j][1]) pairs
    __shared__ __align__(16) u64 sby[2];
    __shared__ __align__(16) u64 sWp1i[2 * HID];   // (Wp1[0][h], Wp1[1][h]) pairs
    __shared__ __align__(16) u64 sbp1[HID];
    __shared__ __align__(16) u64 sWp2[HID * EE];   // row-major [h][e]
    __shared__ __align__(16) u64 sbp2[EE];
    __shared__ __align__(16) u64 sGxy[2 * EE];     // (Gx[e], Gy[e]) pairs
    __shared__ __align__(16) u64 sTh[EE];          // -TAU * h[e]

    const int tid = threadIdx.x;
    for (int i = tid; i < HID * HID; i += TPB) sW2[i] = pk(W2[i], W2[i]);
    for (int i = tid; i < HID * EE; i += TPB) {
        sWmu[i] = pk(Wmu[i], Wmu[i]);
        sWp2[i] = pk(Wp2[i], Wp2[i]);
    }
    for (int i = tid; i < 2 * HID; i += TPB) {
        float w1 = W1[(i & 1) * HID + (i >> 1)];  sW1i[i]  = pk(w1, w1);
        float wp = Wp1[(i & 1) * HID + (i >> 1)]; sWp1i[i] = pk(wp, wp);
        sWy[i] = pk(Wy[i], Wy[i]);
    }
    for (int i = tid; i < HID; i += TPB) {
        sb1[i]  = pk(b1[i],  b1[i]);
        sb2[i]  = pk(b2[i],  b2[i]);
        sbp1[i] = pk(bp1[i], bp1[i]);
    }
    for (int i = tid; i < 2 * EE; i += TPB) sGxy[i] = pk(G[i], G[i]);
    for (int i = tid; i < EE; i += TPB) {
        sbmu[i] = pk(bmu[i], bmu[i]);
        sbp2[i] = pk(bp2[i], bp2[i]);
        float th = -0.5f * hb[i];  // -TAU*h
        sTh[i] = pk(th, th);
    }
    if (tid < 2) sby[tid] = pk(by[tid], by[tid]);
    __syncthreads();

    const int gid = blockIdx.x * TPB + tid;
    if (gid >= npairs) return;

    // Two adjacent points per thread: x[2g], x[2g+1] as one float4.
    const float4 xv = reinterpret_cast<const float4*>(gx)[gid];
    const u64 xa = pk(xv.x, xv.z);  // x component 0 of both points
    const u64 xb = pk(xv.y, xv.w);  // x component 1 of both points

    // ---------------- encoder: feats2 = relu(relu(x@W1+b1)@W2 + b2) ----------------
    u64 f2[HID];
    #pragma unroll
    for (int j = 0; j < HID; j += 2) {
        ulonglong2 b = *reinterpret_cast<const ulonglong2*>(&sb2[j]);
        f2[j] = b.x; f2[j + 1] = b.y;
    }
    #pragma unroll
    for (int k = 0; k < HID; ++k) {
        ulonglong2 w1 = *reinterpret_cast<const ulonglong2*>(&sW1i[2 * k]);
        u64 f1 = relu2(fma2(xa, w1.x, fma2(xb, w1.y, sb1[k])));
        #pragma unroll
        for (int j = 0; j < HID; j += 2) {
            ulonglong2 w = *reinterpret_cast<const ulonglong2*>(&sW2[k * HID + j]);
            f2[j]     = fma2(f1, w.x, f2[j]);
            f2[j + 1] = fma2(f1, w.y, f2[j + 1]);
        }
    }

    // ---------------- heads: mu = relu(f@Wmu+bmu), y = tanh(f@Wy+by) ----------------
    u64 mu[EE], y0, y1;
    #pragma unroll
    for (int e = 0; e < EE; ++e) mu[e] = sbmu[e];
    y0 = sby[0]; y1 = sby[1];
    #pragma unroll
    for (int j = 0; j < HID; ++j) {
        u64 f = relu2(f2[j]);
        ulonglong2 wy = *reinterpret_cast<const ulonglong2*>(&sWy[2 * j]);
        y0 = fma2(f, wy.x, y0);
        y1 = fma2(f, wy.y, y1);
        #pragma unroll
        for (int e = 0; e < EE; e += 2) {
            ulonglong2 w = *reinterpret_cast<const ulonglong2*>(&sWmu[j * EE + e]);
            mu[e]     = fma2(f, w.x, mu[e]);
            mu[e + 1] = fma2(f, w.y, mu[e + 1]);
        }
    }
    #pragma unroll
    for (int e = 0; e < EE; ++e) mu[e] = relu2(mu[e]);
    {
        float a, b;
        upk(y0, a, b); y0 = pk(tanh_acc(a), tanh_acc(b));
        upk(y1, a, b); y1 = pk(tanh_acc(a), tanh_acc(b));
    }

    const u64 C05 = pk(0.5f, 0.5f);    // TAU == SIGMA == RES == 0.5
    const u64 N05 = pk(-0.5f, -0.5f);

    // ta[e] = TAU * (x . G_e - h_e)
    u64 ta[EE];
    #pragma unroll
    for (int e = 0; e < EE; ++e) {
        ulonglong2 g = *reinterpret_cast<const ulonglong2*>(&sGxy[2 * e]);
        u64 xg = fma2(xa, g.x, mul2(xb, g.y));
        ta[e] = fma2(C05, xg, sTh[e]);
    }

    // ---------------- 10 PDHG steps (rolled: keep body inside I-cache) ----------------
    #pragma unroll 1
    for (int it = 0; it < JSTEPS; ++it) {
        // v = mu @ G ; y = normalize_ball(y + SIGMA*v)
        u64 v0, v1;
        {
            ulonglong2 g0 = *reinterpret_cast<const ulonglong2*>(&sGxy[0]);
            v0 = mul2(mu[0], g0.x); v1 = mul2(mu[0], g0.y);
            #pragma unroll
            for (int e = 1; e < EE; ++e) {
                ulonglong2 g = *reinterpret_cast<const ulonglong2*>(&sGxy[2 * e]);
                v0 = fma2(mu[e], g.x, v0);
                v1 = fma2(mu[e], g.y, v1);
            }
        }
        y0 = fma2(C05, v0, y0);
        y1 = fma2(C05, v1, y1);
        {
            u64 n2 = fma2(y0, y0, mul2(y1, y1));
            float na, nb; upk(n2, na, nb);
            float sa = (na > 1.0f) ? rsqrtf(na) : 1.0f;
            float sb = (nb > 1.0f) ? rsqrtf(nb) : 1.0f;
            u64 s = pk(sa, sb);
            y0 = mul2(y0, s); y1 = mul2(y1, s);
        }
        // mu += TAU*a - TAU*(y @ G^T)
        #pragma unroll
        for (int e = 0; e < EE; ++e) {
            ulonglong2 g = *reinterpret_cast<const ulonglong2*>(&sGxy[2 * e]);
            u64 yg = fma2(y0, g.x, mul2(y1, g.y));
            mu[e] = add2(mu[e], fma2(N05, yg, ta[e]));
        }
        // z = mu @ G
        u64 z0, z1;
        {
            ulonglong2 g0 = *reinterpret_cast<const ulonglong2*>(&sGxy[0]);
            z0 = mul2(mu[0], g0.x); z1 = mul2(mu[0], g0.y);
            #pragma unroll
            for (int e = 1; e < EE; ++e) {
                ulonglong2 g = *reinterpret_cast<const ulonglong2*>(&sGxy[2 * e]);
                z0 = fma2(mu[e], g.x, z0);
                z1 = fma2(mu[e], g.y, z1);
            }
        }
        // delta = relu(z@Wp1 + bp1) @ Wp2 + bp2   (dominant: 512 MAC/step)
        u64 d[EE];
        #pragma unroll
        for (int e = 0; e < EE; e += 2) {
            ulonglong2 b = *reinterpret_cast<const ulonglong2*>(&sbp2[e]);
            d[e] = b.x; d[e + 1] = b.y;
        }
        #pragma unroll
        for (int hh = 0; hh < HID; ++hh) {
            ulonglong2 wp = *reinterpret_cast<const ulonglong2*>(&sWp1i[2 * hh]);
            u64 hv = relu2(fma2(z0, wp.x, fma2(z1, wp.y, sbp1[hh])));
            #pragma unroll
            for (int e = 0; e < EE; e += 2) {
                ulonglong2 w = *reinterpret_cast<const ulonglong2*>(&sWp2[hh * EE + e]);
                d[e]     = fma2(hv, w.x, d[e]);
                d[e + 1] = fma2(hv, w.y, d[e + 1]);
            }
        }
        // mu = project_mu(mu + RES*delta): clamp >= 0, then scale so ||mu@G|| <= 1
        #pragma unroll
        for (int e = 0; e < EE; ++e) mu[e] = relu2(fma2(C05, d[e], mu[e]));
        {
            ulonglong2 g0 = *reinterpret_cast<const ulonglong2*>(&sGxy[0]);
            v0 = mul2(mu[0], g0.x); v1 = mul2(mu[0], g0.y);
            #pragma unroll
            for (int e = 1; e < EE; ++e) {
                ulonglong2 g = *reinterpret_cast<const ulonglong2*>(&sGxy[2 * e]);
                v0 = fma2(mu[e], g.x, v0);
                v1 = fma2(mu[e], g.y, v1);
            }
            u64 n2 = fma2(v0, v0, mul2(v1, v1));
            float na, nb; upk(n2, na, nb);
            float sa = (na > 1.0f) ? rsqrtf(na) : 1.0f;
            float sb = (nb > 1.0f) ? rsqrtf(nb) : 1.0f;
            u64 s = pk(sa, sb);
            #pragma unroll
            for (int e = 0; e < EE; ++e) mu[e] = mul2(mu[e], s);
        }
    }

    // ---------------- final project_mu (mu already >= 0 from loop) ----------------
    {
        ulonglong2 g0 = *reinterpret_cast<const ulonglong2*>(&sGxy[0]);
        u64 v0 = mul2(mu[0], g0.x), v1 = mul2(mu[0], g0.y);
        #pragma unroll
        for (int e = 1; e < EE; ++e) {
            ulonglong2 g = *reinterpret_cast<const ulonglong2*>(&sGxy[2 * e]);
            v0 = fma2(mu[e], g.x, v0);
            v1 = fma2(mu[e], g.y, v1);
        }
        u64 n2 = fma2(v0, v0, mul2(v1, v1));
        float na, nb; upk(n2, na, nb);
        float sa = (na > 1.0f) ? rsqrtf(na) : 1.0f;
        float sb = (nb > 1.0f) ? rsqrtf(nb) : 1.0f;
        u64 s = pk(sa, sb);
        #pragma unroll
        for (int e = 0; e < EE; ++e) mu[e] = mul2(mu[e], s);
    }

    // ---------------- store: rows 2g and 2g+1 are 128B contiguous ----------------
    float r0[EE], r1[EE];
    #pragma unroll
    for (int e = 0; e < EE; ++e) upk(mu[e], r0[e], r1[e]);
    float4* o = reinterpret_cast<float4*>(out + (size_t)gid * 32);
    o[0] = make_float4(r0[0],  r0[1],  r0[2],  r0[3]);
    o[1] = make_float4(r0[4],  r0[5],  r0[6],  r0[7]);
    o[2] = make_float4(r0[8],  r0[9],  r0[10], r0[11]);
    o[3] = make_float4(r0[12], r0[13], r0[14], r0[15]);
    o[4] = make_float4(r1[0],  r1[1],  r1[2],  r1[3]);
    o[5] = make_float4(r1[4],  r1[5],  r1[6],  r1[7]);
    o[6] = make_float4(r1[8],  r1[9],  r1[10], r1[11]);
    o[7] = make_float4(r1[12], r1[13], r1[14], r1[15]);
}

extern "C" void kernel_launch(void* const* d_in, const int* in_sizes, int n_in,
                              void* d_out, int out_size) {
    (void)n_in; (void)out_size;
    const float* x   = (const float*)d_in[0];
    const float* G   = (const float*)d_in[1];
    const float* h   = (const float*)d_in[2];
    const float* W1  = (const float*)d_in[3];
    const float* b1  = (const float*)d_in[4];
    const float* W2  = (const float*)d_in[5];
    const float* b2  = (const float*)d_in[6];
    const float* Wmu = (const float*)d_in[7];
    const float* bmu = (const float*)d_in[8];
    const float* Wy  = (const float*)d_in[9];
    const float* by  = (const float*)d_in[10];
    const float* Wp1 = (const float*)d_in[11];
    const float* bp1 = (const float*)d_in[12];
    const float* Wp2 = (const float*)d_in[13];
    const float* bp2 = (const float*)d_in[14];

    const int n_points = in_sizes[0] / 2;   // x is [N, 2]
    const int npairs   = n_points / 2;      // 2 points per thread
    const int nblocks  = (npairs + TPB - 1) / TPB;

    pdhg_kernel<<<nblocks, TPB>>>(x, G, h, W1, b1, W2, b2, Wmu, bmu,
                                  Wy, by, Wp1, bp1, Wp2, bp2,
                                  (float*)d_out, npairs);
}